// round 1
// baseline (speedup 1.0000x reference)
#include <cuda_runtime.h>

// MultiCellLSTM: B=4096 rows, T=512 steps, H=64, gates 4H=256.
// Persistent per-CTA recurrence: 128 CTAs x 256 threads, 32 rows/CTA.
// f32x2 packed FMA (fma.rn.f32x2), weights resident in smem (swizzled,
// conflict-free), h double-buffered in smem, c-state in registers.

#define Hh    64
#define BB    4096
#define TT    512
#define NROW  32
#define NTHR  256
#define NCTA  (BB / NROW)          // 128
#define HSTR  68                   // padded h row stride (floats)
#define WS_F2 (3 * 64 * 128)       // recurrent weights, float2 pairs
#define CMB_F2 (3 * 4 * 128)       // bias + input weights, float2 pairs
#define HBUF_F (2 * NROW * HSTR)   // double-buffered h

typedef unsigned long long u64;

__device__ __forceinline__ float ex2f(float x) { float y; asm("ex2.approx.f32 %0, %1;" : "=f"(y) : "f"(x)); return y; }
__device__ __forceinline__ float rcpf(float x) { float y; asm("rcp.approx.f32 %0, %1;" : "=f"(y) : "f"(x)); return y; }
__device__ __forceinline__ float sigf(float x) { return rcpf(1.0f + ex2f(-1.4426950408889634f * x)); }
__device__ __forceinline__ float tnhf(float x) { return fmaf(2.0f, rcpf(1.0f + ex2f(-2.8853900817779268f * x)), -1.0f); }

__device__ __forceinline__ u64 pk2(float a, float b) { u64 r; asm("mov.b64 %0, {%1, %2};" : "=l"(r) : "f"(a), "f"(b)); return r; }
__device__ __forceinline__ void up2(u64 v, float& a, float& b) { asm("mov.b64 {%0, %1}, %2;" : "=f"(a), "=f"(b) : "l"(v)); }
__device__ __forceinline__ u64 ffma2(u64 a, u64 b, u64 c) { u64 d; asm("fma.rn.f32x2 %0, %1, %2, %3;" : "=l"(d) : "l"(a), "l"(b), "l"(c)); return d; }

// One LSTM step for cell type TY (0: x1+x2+x3, 1: x1+x2, 2: x1).
// Thread owns hidden units 8c..8c+7: acc layout = [class q=i,f,g,o][pair 0..3].
template<int TY>
__device__ __forceinline__ void do_step(
    const char* __restrict__ wsB,   // ws2 base (bytes)
    const char* __restrict__ cmB,   // cmb2 base (bytes)
    const float* __restrict__ hcur, // this row's current h (row base)
    float* __restrict__ hnxtT,      // this thread's h output slot (row base + c*8)
    int offA, int offB, int cOff,
    float xv1, float xv2, float xv3,
    float (&cst)[8], float (&hreg)[8])
{
    const char* wcell = wsB + TY * 65536;   // 64 k-rows * 1024B
    const char* ccell = cmB + TY * 4096;    // 4 arrays * 1024B

    u64 acc[16];

    // init: bias (+bhh folded at fill time)
    #pragma unroll
    for (int q = 0; q < 4; q++) {
        ulonglong2 b0 = *(const ulonglong2*)(ccell + q * 256 + cOff);
        ulonglong2 b1 = *(const ulonglong2*)(ccell + q * 256 + cOff + 16);
        acc[q * 4 + 0] = b0.x; acc[q * 4 + 1] = b0.y;
        acc[q * 4 + 2] = b1.x; acc[q * 4 + 3] = b1.y;
    }
    // + Wi[:,0] * x1
    {
        u64 xd = pk2(xv1, xv1);
        #pragma unroll
        for (int q = 0; q < 4; q++) {
            ulonglong2 w0 = *(const ulonglong2*)(ccell + 1024 + q * 256 + cOff);
            ulonglong2 w1 = *(const ulonglong2*)(ccell + 1024 + q * 256 + cOff + 16);
            acc[q * 4 + 0] = ffma2(w0.x, xd, acc[q * 4 + 0]);
            acc[q * 4 + 1] = ffma2(w0.y, xd, acc[q * 4 + 1]);
            acc[q * 4 + 2] = ffma2(w1.x, xd, acc[q * 4 + 2]);
            acc[q * 4 + 3] = ffma2(w1.y, xd, acc[q * 4 + 3]);
        }
    }
    if (TY <= 1) {  // + Wi[:,1] * x2
        u64 xd = pk2(xv2, xv2);
        #pragma unroll
        for (int q = 0; q < 4; q++) {
            ulonglong2 w0 = *(const ulonglong2*)(ccell + 2048 + q * 256 + cOff);
            ulonglong2 w1 = *(const ulonglong2*)(ccell + 2048 + q * 256 + cOff + 16);
            acc[q * 4 + 0] = ffma2(w0.x, xd, acc[q * 4 + 0]);
            acc[q * 4 + 1] = ffma2(w0.y, xd, acc[q * 4 + 1]);
            acc[q * 4 + 2] = ffma2(w1.x, xd, acc[q * 4 + 2]);
            acc[q * 4 + 3] = ffma2(w1.y, xd, acc[q * 4 + 3]);
        }
    }
    if (TY == 0) {  // + Wi[:,2] * x3
        u64 xd = pk2(xv3, xv3);
        #pragma unroll
        for (int q = 0; q < 4; q++) {
            ulonglong2 w0 = *(const ulonglong2*)(ccell + 3072 + q * 256 + cOff);
            ulonglong2 w1 = *(const ulonglong2*)(ccell + 3072 + q * 256 + cOff + 16);
            acc[q * 4 + 0] = ffma2(w0.x, xd, acc[q * 4 + 0]);
            acc[q * 4 + 1] = ffma2(w0.y, xd, acc[q * 4 + 1]);
            acc[q * 4 + 2] = ffma2(w1.x, xd, acc[q * 4 + 2]);
            acc[q * 4 + 3] = ffma2(w1.y, xd, acc[q * 4 + 3]);
        }
    }

    // recurrent: acc += Wh[:,k] * h[k], k = 0..63
    #pragma unroll 2
    for (int kk = 0; kk < Hh; kk += 4) {
        float4 hv = *(const float4*)(hcur + kk);
        float hs[4] = {hv.x, hv.y, hv.z, hv.w};
        #pragma unroll
        for (int j = 0; j < 4; j++) {
            u64 hd = pk2(hs[j], hs[j]);
            const char* base = wcell + (kk + j) * 1024;
            #pragma unroll
            for (int q = 0; q < 4; q++) {
                ulonglong2 wa = *(const ulonglong2*)(base + q * 256 + offA);
                ulonglong2 wb = *(const ulonglong2*)(base + q * 256 + offB);
                acc[q * 4 + 0] = ffma2(wa.x, hd, acc[q * 4 + 0]);
                acc[q * 4 + 1] = ffma2(wa.y, hd, acc[q * 4 + 1]);
                acc[q * 4 + 2] = ffma2(wb.x, hd, acc[q * 4 + 2]);
                acc[q * 4 + 3] = ffma2(wb.y, hd, acc[q * 4 + 3]);
            }
        }
    }

    // elementwise LSTM cell
    float gi[8], gf[8], gg[8], go[8];
    #pragma unroll
    for (int m = 0; m < 4; m++) {
        up2(acc[m],      gi[2 * m], gi[2 * m + 1]);
        up2(acc[4 + m],  gf[2 * m], gf[2 * m + 1]);
        up2(acc[8 + m],  gg[2 * m], gg[2 * m + 1]);
        up2(acc[12 + m], go[2 * m], go[2 * m + 1]);
    }
    #pragma unroll
    for (int u = 0; u < 8; u++) {
        float cn = fmaf(sigf(gf[u]), cst[u], sigf(gi[u]) * tnhf(gg[u]));
        cst[u] = cn;
        hreg[u] = sigf(go[u]) * tnhf(cn);
    }
    *(float4*)(hnxtT)     = make_float4(hreg[0], hreg[1], hreg[2], hreg[3]);
    *(float4*)(hnxtT + 4) = make_float4(hreg[4], hreg[5], hreg[6], hreg[7]);
}

__global__ __launch_bounds__(NTHR, 1) void mclstm_kernel(
    const float* __restrict__ x1, const float* __restrict__ x2, const float* __restrict__ x3,
    const float* __restrict__ Wih3, const float* __restrict__ Whh3,
    const float* __restrict__ bih3, const float* __restrict__ bhh3,
    const float* __restrict__ Wih2, const float* __restrict__ Whh2,
    const float* __restrict__ bih2, const float* __restrict__ bhh2,
    const float* __restrict__ Wih1, const float* __restrict__ Whh1,
    const float* __restrict__ bih1, const float* __restrict__ bhh1,
    const float* __restrict__ Wout, const float* __restrict__ bOut,
    float* __restrict__ out)
{
    extern __shared__ float smemf[];
    float2* ws2  = (float2*)smemf;
    float2* cmb2 = ws2 + WS_F2;
    float*  hbuf = (float*)(cmb2 + CMB_F2);

    const int tid = threadIdx.x;

    // ---- stage recurrent weights into smem (paired + bank-swizzled) ----
    // pair p covers gates (2p, 2p+1). Storage byte offset within a k-row:
    //   q*256 + c*32 + (h ^ (c>>2))*16 + col*8   (q=class, c=chunk, h=half)
    // The half-swap for c>=4 makes the 8 chunk addresses tile all 32 banks.
    for (int idx = tid; idx < WS_F2; idx += NTHR) {
        int ty = idx >> 13; int rem = idx & 8191;
        int k = rem >> 7;   int p = rem & 127;
        const float* W = (ty == 0) ? Whh3 : (ty == 1) ? Whh2 : Whh1;
        float2 v;
        v.x = W[(2 * p) * Hh + k];
        v.y = W[(2 * p + 1) * Hh + k];
        int q = p >> 5, w5 = p & 31, cc = w5 >> 2, j = w5 & 3;
        int hh = j >> 1, col = j & 1;
        int slot = q * 32 + cc * 4 + ((hh ^ (cc >> 2)) & 1) * 2 + col;
        ws2[(ty * 64 + k) * 128 + slot] = v;
    }
    // ---- stage bias (bih+bhh) and input-weight columns ----
    for (int idx = tid; idx < 3 * 128; idx += NTHR) {
        int ty = idx >> 7; int p = idx & 127;
        int j0 = 2 * p, j1 = 2 * p + 1;
        const float *bi, *bh, *wi; int wic;
        if (ty == 0)      { bi = bih3; bh = bhh3; wi = Wih3; wic = 3; }
        else if (ty == 1) { bi = bih2; bh = bhh2; wi = Wih2; wic = 2; }
        else              { bi = bih1; bh = bhh1; wi = Wih1; wic = 1; }
        float2 b2; b2.x = bi[j0] + bh[j0]; b2.y = bi[j1] + bh[j1];
        cmb2[(ty * 4 + 0) * 128 + p] = b2;
        float2 w0; w0.x = wi[j0 * wic]; w0.y = wi[j1 * wic];
        cmb2[(ty * 4 + 1) * 128 + p] = w0;
        float2 w1 = make_float2(0.f, 0.f);
        if (wic > 1) { w1.x = wi[j0 * wic + 1]; w1.y = wi[j1 * wic + 1]; }
        cmb2[(ty * 4 + 2) * 128 + p] = w1;
        float2 w2 = make_float2(0.f, 0.f);
        if (wic > 2) { w2.x = wi[j0 * wic + 2]; w2.y = wi[j1 * wic + 2]; }
        cmb2[(ty * 4 + 3) * 128 + p] = w2;
    }
    for (int idx = tid; idx < HBUF_F; idx += NTHR) hbuf[idx] = 0.f;
    __syncthreads();

    const int c   = tid & 7;    // chunk: hidden units 8c..8c+7
    const int rl  = tid >> 3;   // local row
    const int row = blockIdx.x * NROW + rl;

    const int sA   = ((c >> 2) & 1) * 16;
    const int cOff = c * 32;
    const int offA = cOff + sA;        // half 0 (pairs 4c,4c+1)
    const int offB = cOff + 16 - sA;   // half 1 (pairs 4c+2,4c+3)

    float cst[8], hreg[8];
    #pragma unroll
    for (int u = 0; u < 8; u++) { cst[u] = 0.f; hreg[u] = 0.f; }

    const float* x1r = x1 + (size_t)row * TT;
    const float* x2r = x2 + (size_t)row * (TT / 2);
    const float* x3r = x3 + (size_t)row * (TT / 4);

    float4 xa = *(const float4*)(x1r);
    float2 xb = *(const float2*)(x2r);
    float  xc = x3r[0];

    const char* wsB = (const char*)ws2;
    const char* cmB = (const char*)cmb2;

    int par = 0;

#define STEP(TYV, A1, A2, A3)                                                   \
    {                                                                           \
        const float* hc = hbuf + par * (NROW * HSTR) + rl * HSTR;               \
        float* hn = hbuf + (par ^ 1) * (NROW * HSTR) + rl * HSTR + c * 8;       \
        do_step<TYV>(wsB, cmB, hc, hn, offA, offB, cOff, (A1), (A2), (A3),      \
                     cst, hreg);                                                \
        __syncthreads();                                                        \
        par ^= 1;                                                               \
    }

    for (int b = 0; b < TT / 4; b++) {
        // prefetch next 4-step block of inputs (hides gmem/L2 latency)
        int bn = min(b + 1, TT / 4 - 1);
        float4 nxa = *(const float4*)(x1r + bn * 4);
        float2 nxb = *(const float2*)(x2r + bn * 2);
        float  nxc = x3r[bn];

        STEP(0, xa.x, xb.x, xc);     // t%4==0: cell3 (x1,x2,x3)
        STEP(2, xa.y, 0.f, 0.f);     // t%4==1: cell1 (x1)
        STEP(1, xa.z, xb.y, 0.f);    // t%4==2: cell2 (x1,x2)
        STEP(2, xa.w, 0.f, 0.f);     // t%4==3: cell1 (x1)

        xa = nxa; xb = nxb; xc = nxc;
    }
#undef STEP

    // out[row] = sigmoid(h . Wout + bOut): reduce over the row's 8 chunks
    float pw = 0.f;
    #pragma unroll
    for (int u = 0; u < 8; u++) pw = fmaf(hreg[u], Wout[c * 8 + u], pw);
    pw += __shfl_xor_sync(0xffffffffu, pw, 1);
    pw += __shfl_xor_sync(0xffffffffu, pw, 2);
    pw += __shfl_xor_sync(0xffffffffu, pw, 4);
    if (c == 0) out[row] = sigf(pw + bOut[0]);
}

extern "C" void kernel_launch(void* const* d_in, const int* in_sizes, int n_in,
                              void* d_out, int out_size) {
    const float* x1   = (const float*)d_in[0];
    const float* x2   = (const float*)d_in[1];
    const float* x3   = (const float*)d_in[2];
    const float* Wih3 = (const float*)d_in[3];
    const float* Whh3 = (const float*)d_in[4];
    const float* bih3 = (const float*)d_in[5];
    const float* bhh3 = (const float*)d_in[6];
    const float* Wih2 = (const float*)d_in[7];
    const float* Whh2 = (const float*)d_in[8];
    const float* bih2 = (const float*)d_in[9];
    const float* bhh2 = (const float*)d_in[10];
    const float* Wih1 = (const float*)d_in[11];
    const float* Whh1 = (const float*)d_in[12];
    const float* bih1 = (const float*)d_in[13];
    const float* bhh1 = (const float*)d_in[14];
    const float* Wout = (const float*)d_in[15];
    const float* bOut = (const float*)d_in[16];

    size_t smem = sizeof(float2) * (WS_F2 + CMB_F2) + sizeof(float) * HBUF_F; // 226304 B
    cudaFuncSetAttribute(mclstm_kernel, cudaFuncAttributeMaxDynamicSharedMemorySize, (int)smem);

    mclstm_kernel<<<NCTA, NTHR, smem>>>(
        x1, x2, x3,
        Wih3, Whh3, bih3, bhh3,
        Wih2, Whh2, bih2, bhh2,
        Wih1, Whh1, bih1, bhh1,
        Wout, bOut, (float*)d_out);
}

// round 2
// speedup vs baseline: 2.3600x; 2.3600x over previous
#include <cuda_runtime.h>

// MultiCellLSTM: B=4096, T=512, H=64, gates 4H=256.
// R2: warp-private rows (4 rows/warp), lane owns units {2l,2l+1} x 4 rows.
// Weight LDS.128 now delivers 512B of distinct data (crossbar /4 vs R1).
// h stored pre-duplicated in warp-private smem -> broadcast LDS.128 gives
// two ready f32x2 multiplicands. Sync-free main loop (only __syncwarp).

typedef unsigned long long u64;

#define NTHR   256
#define NCTA   128
#define WS_U64 (3 * 64 * 128)   // 24576 u64 : recurrent weights
#define CMB_U64 (3 * 4 * 128)   // 1536  u64 : bias + input-weight cols
#define HD_U64 (32 * 64)        // 2048  u64 : duplicated h, 32 rows x 64 units
#define SMEM_BYTES ((WS_U64 + CMB_U64 + HD_U64) * 8)  // 225280

__device__ __forceinline__ float ex2f(float x) { float y; asm("ex2.approx.f32 %0, %1;" : "=f"(y) : "f"(x)); return y; }
__device__ __forceinline__ float rcpf(float x) { float y; asm("rcp.approx.f32 %0, %1;" : "=f"(y) : "f"(x)); return y; }
__device__ __forceinline__ float sigf(float x) { return rcpf(1.0f + ex2f(-1.4426950408889634f * x)); }
__device__ __forceinline__ float tnhf(float x) { return fmaf(2.0f, rcpf(1.0f + ex2f(-2.8853900817779268f * x)), -1.0f); }

__device__ __forceinline__ u64 pk2(float a, float b) { u64 r; asm("mov.b64 %0, {%1, %2};" : "=l"(r) : "f"(a), "f"(b)); return r; }
__device__ __forceinline__ void up2(u64 v, float& a, float& b) { asm("mov.b64 {%0, %1}, %2;" : "=f"(a), "=f"(b) : "l"(v)); }
__device__ __forceinline__ u64 ffma2(u64 a, u64 b, u64 c) { u64 d; asm("fma.rn.f32x2 %0, %1, %2, %3;" : "=l"(d) : "l"(a), "l"(b), "l"(c)); return d; }

// One LSTM step for cell type TY (0: x1+x2+x3, 1: x1+x2, 2: x1 only).
// Lane owns units {2l,2l+1}; processes 4 rows. Weight k-row layout (1024B):
//   physical 16B slot = l*32 + ((h ^ (l>>2))&1)*16, h=0 -> classes(i,f), h=1 -> (g,o).
// The half-swap makes each 8-lane phase of an LDS.128 tile all 32 banks once.
template<int TY>
__device__ __forceinline__ void do_step(
    const char* __restrict__ wsB, const char* __restrict__ cmB,
    char* __restrict__ hb,                  // this warp's dup'd-h base
    int offA, int offB, int lane,
    const float (&xv1)[4], const float (&xv2)[4], const float (&xv3)[4],
    float (&cst)[4][2], float (&hl)[4][2])
{
    const char* wcell = wsB + TY * 65536;   // 64 k-rows * 1024B
    const char* cc    = cmB + TY * 4096;    // 4 arrays * 1024B

    u64 acc[4][4];  // [class i,f,g,o][row]

    {   // bias (bih+bhh prefolded)
        ulonglong2 bA = *(const ulonglong2*)(cc + offA);
        ulonglong2 bB = *(const ulonglong2*)(cc + offB);
        #pragma unroll
        for (int r = 0; r < 4; r++) { acc[0][r] = bA.x; acc[1][r] = bA.y; acc[2][r] = bB.x; acc[3][r] = bB.y; }
    }
    {   // + Wi[:,0] * x1
        ulonglong2 wA = *(const ulonglong2*)(cc + 1024 + offA);
        ulonglong2 wB = *(const ulonglong2*)(cc + 1024 + offB);
        #pragma unroll
        for (int r = 0; r < 4; r++) {
            u64 xd = pk2(xv1[r], xv1[r]);
            acc[0][r] = ffma2(wA.x, xd, acc[0][r]); acc[1][r] = ffma2(wA.y, xd, acc[1][r]);
            acc[2][r] = ffma2(wB.x, xd, acc[2][r]); acc[3][r] = ffma2(wB.y, xd, acc[3][r]);
        }
    }
    if (TY <= 1) {  // + Wi[:,1] * x2
        ulonglong2 wA = *(const ulonglong2*)(cc + 2048 + offA);
        ulonglong2 wB = *(const ulonglong2*)(cc + 2048 + offB);
        #pragma unroll
        for (int r = 0; r < 4; r++) {
            u64 xd = pk2(xv2[r], xv2[r]);
            acc[0][r] = ffma2(wA.x, xd, acc[0][r]); acc[1][r] = ffma2(wA.y, xd, acc[1][r]);
            acc[2][r] = ffma2(wB.x, xd, acc[2][r]); acc[3][r] = ffma2(wB.y, xd, acc[3][r]);
        }
    }
    if (TY == 0) {  // + Wi[:,2] * x3
        ulonglong2 wA = *(const ulonglong2*)(cc + 3072 + offA);
        ulonglong2 wB = *(const ulonglong2*)(cc + 3072 + offB);
        #pragma unroll
        for (int r = 0; r < 4; r++) {
            u64 xd = pk2(xv3[r], xv3[r]);
            acc[0][r] = ffma2(wA.x, xd, acc[0][r]); acc[1][r] = ffma2(wA.y, xd, acc[1][r]);
            acc[2][r] = ffma2(wB.x, xd, acc[2][r]); acc[3][r] = ffma2(wB.y, xd, acc[3][r]);
        }
    }

    // recurrent: k processed in pairs; hd LDS.128 yields (dup h_2m, dup h_2m+1)
    #pragma unroll 4
    for (int m = 0; m < 32; m++) {
        const char* base = wcell + m * 2048;
        ulonglong2 w0A = *(const ulonglong2*)(base + offA);
        ulonglong2 w0B = *(const ulonglong2*)(base + offB);
        ulonglong2 w1A = *(const ulonglong2*)(base + 1024 + offA);
        ulonglong2 w1B = *(const ulonglong2*)(base + 1024 + offB);
        #pragma unroll
        for (int r = 0; r < 4; r++) {
            ulonglong2 hd = *(const ulonglong2*)(hb + r * 512 + m * 16);
            acc[0][r] = ffma2(w0A.x, hd.x, acc[0][r]);
            acc[1][r] = ffma2(w0A.y, hd.x, acc[1][r]);
            acc[2][r] = ffma2(w0B.x, hd.x, acc[2][r]);
            acc[3][r] = ffma2(w0B.y, hd.x, acc[3][r]);
            acc[0][r] = ffma2(w1A.x, hd.y, acc[0][r]);
            acc[1][r] = ffma2(w1A.y, hd.y, acc[1][r]);
            acc[2][r] = ffma2(w1B.x, hd.y, acc[2][r]);
            acc[3][r] = ffma2(w1B.y, hd.y, acc[3][r]);
        }
    }

    __syncwarp();  // all lanes done READING h(t)
    #pragma unroll
    for (int r = 0; r < 4; r++) {
        float gi0, gi1, gf0, gf1, gg0, gg1, go0, go1;
        up2(acc[0][r], gi0, gi1);
        up2(acc[1][r], gf0, gf1);
        up2(acc[2][r], gg0, gg1);
        up2(acc[3][r], go0, go1);
        float c0 = fmaf(sigf(gf0), cst[r][0], sigf(gi0) * tnhf(gg0));
        float c1 = fmaf(sigf(gf1), cst[r][1], sigf(gi1) * tnhf(gg1));
        cst[r][0] = c0; cst[r][1] = c1;
        float h0 = sigf(go0) * tnhf(c0);
        float h1 = sigf(go1) * tnhf(c1);
        hl[r][0] = h0; hl[r][1] = h1;
        ulonglong2 st; st.x = pk2(h0, h0); st.y = pk2(h1, h1);
        *(ulonglong2*)(hb + r * 512 + lane * 16) = st;   // dup'd store
    }
    __syncwarp();  // h(t+1) visible to all lanes
}

__global__ __launch_bounds__(NTHR, 1) void mclstm_kernel(
    const float* __restrict__ x1, const float* __restrict__ x2, const float* __restrict__ x3,
    const float* __restrict__ Wih3, const float* __restrict__ Whh3,
    const float* __restrict__ bih3, const float* __restrict__ bhh3,
    const float* __restrict__ Wih2, const float* __restrict__ Whh2,
    const float* __restrict__ bih2, const float* __restrict__ bhh2,
    const float* __restrict__ Wih1, const float* __restrict__ Whh1,
    const float* __restrict__ bih1, const float* __restrict__ bhh1,
    const float* __restrict__ Wout, const float* __restrict__ bOut,
    float* __restrict__ out)
{
    extern __shared__ u64 sm[];
    u64* ws   = sm;
    u64* cmb  = ws + WS_U64;
    u64* hdup = cmb + CMB_U64;

    const int tid = threadIdx.x;

    // ---- stage recurrent weights: ws[(ty*64+k)*128 + slot] ----
    // slot s -> lane l=s>>2, 16B half swz=(s>>1)&1, col=s&1;
    // logical half h = swz ^ ((l>>2)&1); class q = 2h+col; units (2l, 2l+1).
    for (int idx = tid; idx < WS_U64; idx += NTHR) {
        int ty = idx >> 13, rem = idx & 8191, k = rem >> 7, s = rem & 127;
        int l = s >> 2, swz = (s >> 1) & 1, col = s & 1;
        int h = swz ^ ((l >> 2) & 1);
        int q = 2 * h + col;
        const float* W = (ty == 0) ? Whh3 : (ty == 1) ? Whh2 : Whh1;
        int g0 = (q * 64 + 2 * l) * 64 + k;
        ws[idx] = pk2(W[g0], W[g0 + 64]);
    }
    // ---- stage bias + input-weight cols: cmb[(ty*4+arr)*128 + slot] ----
    for (int idx = tid; idx < CMB_U64; idx += NTHR) {
        int ty = idx >> 9, rem = idx & 511, arr = rem >> 7, s = rem & 127;
        int l = s >> 2, swz = (s >> 1) & 1, col = s & 1;
        int h = swz ^ ((l >> 2) & 1);
        int q = 2 * h + col;
        int j0 = q * 64 + 2 * l, j1 = j0 + 1;
        const float *bi, *bh, *wi; int wic;
        if (ty == 0)      { bi = bih3; bh = bhh3; wi = Wih3; wic = 3; }
        else if (ty == 1) { bi = bih2; bh = bhh2; wi = Wih2; wic = 2; }
        else              { bi = bih1; bh = bhh1; wi = Wih1; wic = 1; }
        float a, b;
        if (arr == 0) { a = bi[j0] + bh[j0]; b = bi[j1] + bh[j1]; }
        else {
            int cx = arr - 1;
            if (cx < wic) { a = wi[j0 * wic + cx]; b = wi[j1 * wic + cx]; }
            else          { a = 0.f; b = 0.f; }
        }
        cmb[idx] = pk2(a, b);
    }
    for (int idx = tid; idx < HD_U64; idx += NTHR) hdup[idx] = 0ull;
    __syncthreads();

    const int lane = tid & 31, w = tid >> 5;
    const int row0 = blockIdx.x * 32 + w * 4;

    const int s0   = ((lane >> 2) & 1) * 16;
    const int offA = lane * 32 + s0;        // classes (i,f)
    const int offB = lane * 32 + 16 - s0;   // classes (g,o)

    const char* wsB = (const char*)ws;
    const char* cmB = (const char*)cmb;
    char* hb = (char*)(hdup + (size_t)w * 4 * 64);   // warp-private, 2KB

    float cst[4][2], hl[4][2];
    #pragma unroll
    for (int r = 0; r < 4; r++) { cst[r][0] = cst[r][1] = 0.f; hl[r][0] = hl[r][1] = 0.f; }

    const float* x1r = x1 + (size_t)row0 * 512;
    const float* x2r = x2 + (size_t)row0 * 256;
    const float* x3r = x3 + (size_t)row0 * 128;

    for (int b = 0; b < 128; b++) {
        float a1[4][4], a2[4][2], a3[4];
        #pragma unroll
        for (int r = 0; r < 4; r++) {
            float4 v = *(const float4*)(x1r + (size_t)r * 512 + b * 4);
            a1[r][0] = v.x; a1[r][1] = v.y; a1[r][2] = v.z; a1[r][3] = v.w;
            float2 u = *(const float2*)(x2r + (size_t)r * 256 + b * 2);
            a2[r][0] = u.x; a2[r][1] = u.y;
            a3[r] = x3r[(size_t)r * 128 + b];
        }
        float t1[4], t2[4];
        #pragma unroll
        for (int r = 0; r < 4; r++) { t1[r] = a1[r][0]; t2[r] = a2[r][0]; }
        do_step<0>(wsB, cmB, hb, offA, offB, lane, t1, t2, a3, cst, hl);   // t%4==0

        #pragma unroll
        for (int r = 0; r < 4; r++) t1[r] = a1[r][1];
        do_step<2>(wsB, cmB, hb, offA, offB, lane, t1, t1, t1, cst, hl);   // t%4==1

        #pragma unroll
        for (int r = 0; r < 4; r++) { t1[r] = a1[r][2]; t2[r] = a2[r][1]; }
        do_step<1>(wsB, cmB, hb, offA, offB, lane, t1, t2, t2, cst, hl);   // t%4==2

        #pragma unroll
        for (int r = 0; r < 4; r++) t1[r] = a1[r][3];
        do_step<2>(wsB, cmB, hb, offA, offB, lane, t1, t1, t1, cst, hl);   // t%4==3
    }

    // out[row] = sigmoid(h . Wout + bOut): lane contributes its 2 units,
    // warp-reduce across 32 lanes per row.
    const float wo0 = Wout[2 * lane], wo1 = Wout[2 * lane + 1];
    const float bo = bOut[0];
    #pragma unroll
    for (int r = 0; r < 4; r++) {
        float pw = hl[r][0] * wo0 + hl[r][1] * wo1;
        pw += __shfl_xor_sync(0xffffffffu, pw, 16);
        pw += __shfl_xor_sync(0xffffffffu, pw, 8);
        pw += __shfl_xor_sync(0xffffffffu, pw, 4);
        pw += __shfl_xor_sync(0xffffffffu, pw, 2);
        pw += __shfl_xor_sync(0xffffffffu, pw, 1);
        if (lane == 0) out[row0 + r] = sigf(pw + bo);
    }
}

extern "C" void kernel_launch(void* const* d_in, const int* in_sizes, int n_in,
                              void* d_out, int out_size) {
    const float* x1   = (const float*)d_in[0];
    const float* x2   = (const float*)d_in[1];
    const float* x3   = (const float*)d_in[2];
    const float* Wih3 = (const float*)d_in[3];
    const float* Whh3 = (const float*)d_in[4];
    const float* bih3 = (const float*)d_in[5];
    const float* bhh3 = (const float*)d_in[6];
    const float* Wih2 = (const float*)d_in[7];
    const float* Whh2 = (const float*)d_in[8];
    const float* bih2 = (const float*)d_in[9];
    const float* bhh2 = (const float*)d_in[10];
    const float* Wih1 = (const float*)d_in[11];
    const float* Whh1 = (const float*)d_in[12];
    const float* bih1 = (const float*)d_in[13];
    const float* bhh1 = (const float*)d_in[14];
    const float* Wout = (const float*)d_in[15];
    const float* bOut = (const float*)d_in[16];

    cudaFuncSetAttribute(mclstm_kernel, cudaFuncAttributeMaxDynamicSharedMemorySize, SMEM_BYTES);

    mclstm_kernel<<<NCTA, NTHR, SMEM_BYTES>>>(
        x1, x2, x3,
        Wih3, Whh3, bih3, bhh3,
        Wih2, Whh2, bih2, bhh2,
        Wih1, Whh1, bih1, bhh1,
        Wout, bOut, (float*)d_out);
}